// round 5
// baseline (speedup 1.0000x reference)
#include <cuda_runtime.h>
#include <cstdint>
#include <cstddef>
#include <math.h>

#define N_NODES 100000
#define N_EDGES 1600000
#define N_POS   200000
#define N_NEG   200000
#define IN_C    128
#define HID_C   128
#define OUT_C   64
#define BN_EPS  1e-5f

// ---------------- scratch (static device globals; no allocation) ----------------
__device__ float g_y[N_NODES * 256];      // fused GEMM output [yl | yr] per node
__device__ float g_hA[N_NODES * HID_C];   // hidden after layer 1
__device__ float g_hB[N_NODES * HID_C];   // hidden after layer 2
__device__ float g_wt[4 * 256 * 128];     // 4 pre-rounded weight panels
__device__ int   g_count[N_NODES];
__device__ int   g_off[N_NODES];
__device__ int   g_cur[N_NODES];
__device__ int   g_part[256];
__device__ int   g_srcs[N_EDGES];

// tf32 round-to-nearest
__device__ __forceinline__ uint32_t f2tf32(float f) {
    uint32_t r;
    asm("cvt.rna.tf32.f32 %0, %1;" : "=r"(r) : "f"(f));
    return r;
}

// ---------------- CSR build ----------------
__global__ void k_count(const int* __restrict__ dst) {
    int i = blockIdx.x * blockDim.x + threadIdx.x;
    if (i < N_EDGES) atomicAdd(&g_count[dst[i]], 1);
}
__global__ void k_scan1() {
    __shared__ int sm[1024];
    int i = blockIdx.x * 1024 + threadIdx.x;
    int v = (i < N_NODES) ? g_count[i] : 0;
    sm[threadIdx.x] = v;
    __syncthreads();
    #pragma unroll
    for (int s = 1; s < 1024; s <<= 1) {
        int t = (threadIdx.x >= s) ? sm[threadIdx.x - s] : 0;
        __syncthreads();
        sm[threadIdx.x] += t;
        __syncthreads();
    }
    if (i < N_NODES) g_off[i] = sm[threadIdx.x] - v;
    if (threadIdx.x == 1023) g_part[blockIdx.x] = sm[1023];
}
__global__ void k_scan2(int nb) {
    if (threadIdx.x == 0 && blockIdx.x == 0) {
        int run = 0;
        for (int j = 0; j < nb; j++) { int t = g_part[j]; g_part[j] = run; run += t; }
    }
}
__global__ void k_scan3() {
    int i = blockIdx.x * 1024 + threadIdx.x;
    if (i < N_NODES) {
        int o = g_off[i] + g_part[blockIdx.x];
        g_off[i] = o;
        g_cur[i] = o;
    }
}
__global__ void k_fill(const int* __restrict__ src, const int* __restrict__ dst) {
    int i = blockIdx.x * blockDim.x + threadIdx.x;
    if (i < N_EDGES) {
        int d = dst[i];
        int p = atomicAdd(&g_cur[d], 1);
        g_srcs[p] = src[i];
    }
}

// -------- weight prep: Wt[2*Mh, K] tf32-rounded; rows 0:Mh = s1^T, Mh: = s2^T ----
__global__ void k_prep(const float* __restrict__ s1, const float* __restrict__ s2,
                       float* __restrict__ wt, int K, int Mh) {
    int i = blockIdx.x * 256 + threadIdx.x;
    int tot = 2 * Mh * K;
    if (i >= tot) return;
    int m = i / K, k = i % K;
    float v = (m < Mh) ? s1[(size_t)k * Mh + m] : s2[(size_t)k * Mh + (m - Mh)];
    wt[i] = __uint_as_float(f2tf32(v));
}

// ---------------- tf32 mma.sync GEMM v2 ----------------
// C[Nrows, NOUT] = A[Nrows, K] @ Wt[NOUT, K]^T.
// CTA 128 rows x 128 cols (grid.y panels). Whole-K B in smem (staged once, weights
// pre-rounded); A in 32-k chunks, register-double-buffered, one sync per chunk.
template<int K>
__global__ __launch_bounds__(256, 2) void k_mma(const float* __restrict__ A,
                                                const float* __restrict__ Wt,
                                                float* __restrict__ C,
                                                int Nrows, int NOUT) {
    constexpr int CH   = K / 32;
    constexpr int BSTR = K + 4;
    constexpr int K4   = K / 4;
    extern __shared__ float sm[];
    float* As = sm;                       // [2][128][36]
    float* Bs = sm + 2 * 128 * 36;        // [128][BSTR]

    const int tid  = threadIdx.x;
    const int lane = tid & 31, wid = tid >> 5;
    const int gid  = lane >> 2, tg = lane & 3;
    const int mrow = (wid & 3) * 32;
    const int ncol = (wid >> 2) * 64;
    const int row0 = blockIdx.x * 128;
    const int col0 = blockIdx.y * 128;

    // stage whole B panel (pre-rounded tf32 bits, plain copy)
    #pragma unroll
    for (int l = 0; l < K4 / 2; l++) {           // 128*K4/256 float4 per thread
        int f = tid + l * 256;
        int r = f / K4, c4 = f % K4;
        float4 v = *(const float4*)(Wt + (size_t)(col0 + r) * K + c4 * 4);
        *(float4*)&Bs[r * BSTR + c4 * 4] = v;
    }

    float4 ra[4];
    // prologue: load A chunk 0
    #pragma unroll
    for (int l = 0; l < 4; l++) {
        int f = tid + l * 256;
        int r = f >> 3, c4 = f & 7;
        int grow = row0 + r;
        ra[l] = make_float4(0.f, 0.f, 0.f, 0.f);
        if (grow < Nrows) ra[l] = *(const float4*)(A + (size_t)grow * K + c4 * 4);
    }
    #pragma unroll
    for (int l = 0; l < 4; l++) {
        int f = tid + l * 256;
        int r = f >> 3, c4 = f & 7;
        float4 t;
        t.x = __uint_as_float(f2tf32(ra[l].x));
        t.y = __uint_as_float(f2tf32(ra[l].y));
        t.z = __uint_as_float(f2tf32(ra[l].z));
        t.w = __uint_as_float(f2tf32(ra[l].w));
        *(float4*)&As[r * 36 + c4 * 4] = t;
    }
    __syncthreads();

    float c[2][8][4];
    #pragma unroll
    for (int mt = 0; mt < 2; mt++)
        #pragma unroll
        for (int nt = 0; nt < 8; nt++)
            #pragma unroll
            for (int j = 0; j < 4; j++) c[mt][nt][j] = 0.f;

    #pragma unroll
    for (int ch = 0; ch < CH; ch++) {
        // prefetch next A chunk into registers
        if (ch + 1 < CH) {
            #pragma unroll
            for (int l = 0; l < 4; l++) {
                int f = tid + l * 256;
                int r = f >> 3, c4 = f & 7;
                int grow = row0 + r;
                ra[l] = make_float4(0.f, 0.f, 0.f, 0.f);
                if (grow < Nrows)
                    ra[l] = *(const float4*)(A + (size_t)grow * K + (ch + 1) * 32 + c4 * 4);
            }
        }
        const float* Ab = As + (ch & 1) * (128 * 36);
        const int kofs = ch * 32;

        #pragma unroll
        for (int ks = 0; ks < 4; ks++) {
            uint32_t a[2][4];
            #pragma unroll
            for (int mt = 0; mt < 2; mt++) {
                int r = mrow + mt * 16 + gid;
                a[mt][0] = __float_as_uint(Ab[r * 36 + ks * 8 + tg]);
                a[mt][1] = __float_as_uint(Ab[(r + 8) * 36 + ks * 8 + tg]);
                a[mt][2] = __float_as_uint(Ab[r * 36 + ks * 8 + tg + 4]);
                a[mt][3] = __float_as_uint(Ab[(r + 8) * 36 + ks * 8 + tg + 4]);
            }
            uint32_t b[8][2];
            #pragma unroll
            for (int nt = 0; nt < 8; nt++) {
                int rn = ncol + nt * 8 + gid;
                b[nt][0] = __float_as_uint(Bs[rn * BSTR + kofs + ks * 8 + tg]);
                b[nt][1] = __float_as_uint(Bs[rn * BSTR + kofs + ks * 8 + tg + 4]);
            }
            #pragma unroll
            for (int mt = 0; mt < 2; mt++)
                #pragma unroll
                for (int nt = 0; nt < 8; nt++)
                    asm volatile(
                        "mma.sync.aligned.m16n8k8.row.col.f32.tf32.tf32.f32 "
                        "{%0,%1,%2,%3}, {%4,%5,%6,%7}, {%8,%9}, {%0,%1,%2,%3};"
                        : "+f"(c[mt][nt][0]), "+f"(c[mt][nt][1]),
                          "+f"(c[mt][nt][2]), "+f"(c[mt][nt][3])
                        : "r"(a[mt][0]), "r"(a[mt][1]), "r"(a[mt][2]), "r"(a[mt][3]),
                          "r"(b[nt][0]), "r"(b[nt][1]));
        }

        if (ch + 1 < CH) {
            float* An = As + ((ch + 1) & 1) * (128 * 36);
            #pragma unroll
            for (int l = 0; l < 4; l++) {
                int f = tid + l * 256;
                int r = f >> 3, c4 = f & 7;
                float4 t;
                t.x = __uint_as_float(f2tf32(ra[l].x));
                t.y = __uint_as_float(f2tf32(ra[l].y));
                t.z = __uint_as_float(f2tf32(ra[l].z));
                t.w = __uint_as_float(f2tf32(ra[l].w));
                *(float4*)&An[r * 36 + c4 * 4] = t;
            }
            __syncthreads();
        }
    }

    // epilogue
    #pragma unroll
    for (int mt = 0; mt < 2; mt++) {
        int r0 = row0 + mrow + mt * 16 + gid;
        int r1 = r0 + 8;
        #pragma unroll
        for (int nt = 0; nt < 8; nt++) {
            int col = col0 + ncol + nt * 8 + 2 * tg;
            if (r0 < Nrows)
                *(float2*)(C + (size_t)r0 * NOUT + col) = make_float2(c[mt][nt][0], c[mt][nt][1]);
            if (r1 < Nrows)
                *(float2*)(C + (size_t)r1 * NOUT + col) = make_float2(c[mt][nt][2], c[mt][nt][3]);
        }
    }
}

// ---------------- fused aggregation + combine (warp per node, MLP-unrolled) ------
template<int C, int STRIDE, bool FULL>
__global__ __launch_bounds__(256) void k_aggw(const float* __restrict__ bl,
                                              const float* __restrict__ gam,
                                              const float* __restrict__ bet,
                                              const float* __restrict__ h_in,
                                              float* __restrict__ h_out,
                                              const float* __restrict__ y) {
    constexpr int V = C / 32;
    int warp = (blockIdx.x * 256 + threadIdx.x) >> 5;
    int lane = threadIdx.x & 31;
    if (warp >= N_NODES) return;
    int n = warp;
    int beg = g_off[n], cnt = g_count[n];

    float acc[V];
    #pragma unroll
    for (int j = 0; j < V; j++) acc[j] = 0.f;

    for (int e0 = 0; e0 < cnt; e0 += 32) {
        int m = min(32, cnt - e0);
        int myidx = (lane < m) ? __ldg(&g_srcs[beg + e0 + lane]) : 0;
        int i = 0;
        for (; i + 4 <= m; i += 4) {
            int s0 = __shfl_sync(0xFFFFFFFFu, myidx, i);
            int s1 = __shfl_sync(0xFFFFFFFFu, myidx, i + 1);
            int s2 = __shfl_sync(0xFFFFFFFFu, myidx, i + 2);
            int s3 = __shfl_sync(0xFFFFFFFFu, myidx, i + 3);
            if (V == 4) {
                float4 v0 = *(const float4*)(y + (size_t)s0 * STRIDE + lane * 4);
                float4 v1 = *(const float4*)(y + (size_t)s1 * STRIDE + lane * 4);
                float4 v2 = *(const float4*)(y + (size_t)s2 * STRIDE + lane * 4);
                float4 v3 = *(const float4*)(y + (size_t)s3 * STRIDE + lane * 4);
                acc[0] += v0.x + v1.x + v2.x + v3.x;
                acc[1] += v0.y + v1.y + v2.y + v3.y;
                acc[2] += v0.z + v1.z + v2.z + v3.z;
                acc[3] += v0.w + v1.w + v2.w + v3.w;
            } else {
                float2 v0 = *(const float2*)(y + (size_t)s0 * STRIDE + lane * 2);
                float2 v1 = *(const float2*)(y + (size_t)s1 * STRIDE + lane * 2);
                float2 v2 = *(const float2*)(y + (size_t)s2 * STRIDE + lane * 2);
                float2 v3 = *(const float2*)(y + (size_t)s3 * STRIDE + lane * 2);
                acc[0] += v0.x + v1.x + v2.x + v3.x;
                acc[1] += v0.y + v1.y + v2.y + v3.y;
            }
        }
        for (; i < m; i++) {
            int s = __shfl_sync(0xFFFFFFFFu, myidx, i);
            if (V == 4) {
                float4 v = *(const float4*)(y + (size_t)s * STRIDE + lane * 4);
                acc[0] += v.x; acc[1] += v.y; acc[2] += v.z; acc[3] += v.w;
            } else {
                float2 v = *(const float2*)(y + (size_t)s * STRIDE + lane * 2);
                acc[0] += v.x; acc[1] += v.y;
            }
        }
    }
    float inv = 1.0f / fmaxf((float)cnt, 1.0f);

    float o[V];
    {
        const float* rr = y + (size_t)n * STRIDE + C + lane * V;
        #pragma unroll
        for (int j = 0; j < V; j++)
            o[j] = acc[j] * inv + bl[lane * V + j] + rr[j];
    }
    if (FULL) {
        const float s = rsqrtf(1.0f + BN_EPS);
        const float* hp = h_in + (size_t)n * C + lane * V;
        #pragma unroll
        for (int j = 0; j < V; j++) {
            int ch = lane * V + j;
            o[j] = fmaxf(o[j] * (gam[ch] * s) + bet[ch], 0.f) + hp[j];
        }
    }
    float* op = h_out + (size_t)n * C + lane * V;
    if (V == 4) *(float4*)op = make_float4(o[0], o[1], o[2], o[V - 1]);
    else        *(float2*)op = make_float2(o[0], o[1]);
}

// ---------------- edge decode: sigmoid(relu(P[s]+Q[d]+be1) . We2 + be2) --------
__global__ void k_decode(const int* __restrict__ sidx, const int* __restrict__ didx, int E,
                         const float* __restrict__ be1,
                         const float* __restrict__ We2, const float* __restrict__ be2,
                         float* __restrict__ out, const float* __restrict__ y) {
    int warp = (blockIdx.x * blockDim.x + threadIdx.x) >> 5;
    int lane = threadIdx.x & 31;
    if (warp >= E) return;
    int s = sidx[warp], d = didx[warp];
    float4 p  = *(const float4*)(y + (size_t)s * 256 + lane * 4);
    float4 q  = *(const float4*)(y + (size_t)d * 256 + 128 + lane * 4);
    float4 bb = *(const float4*)(be1 + lane * 4);
    float4 w  = *(const float4*)(We2 + lane * 4);
    float sum = fmaxf(p.x + q.x + bb.x, 0.f) * w.x
              + fmaxf(p.y + q.y + bb.y, 0.f) * w.y
              + fmaxf(p.z + q.z + bb.z, 0.f) * w.z
              + fmaxf(p.w + q.w + bb.w, 0.f) * w.w;
    #pragma unroll
    for (int o = 16; o; o >>= 1) sum += __shfl_xor_sync(0xFFFFFFFFu, sum, o);
    if (lane == 0) out[warp] = 1.0f / (1.0f + expf(-(sum + be2[0])));
}

// ---------------- host launcher ----------------
extern "C" void kernel_launch(void* const* d_in, const int* in_sizes, int n_in,
                              void* d_out, int out_size) {
    const float* x   = (const float*)d_in[0];
    const int*   ei  = (const int*)d_in[1];
    const int*   pos = (const int*)d_in[2];
    const int*   neg = (const int*)d_in[3];
    const float* Wl1 = (const float*)d_in[4];
    const float* bl1 = (const float*)d_in[5];
    const float* Wr1 = (const float*)d_in[6];
    const float* g1  = (const float*)d_in[7];
    const float* b1  = (const float*)d_in[8];
    const float* Wl2 = (const float*)d_in[9];
    const float* bl2 = (const float*)d_in[10];
    const float* Wr2 = (const float*)d_in[11];
    const float* g2  = (const float*)d_in[12];
    const float* b2  = (const float*)d_in[13];
    const float* Wl3 = (const float*)d_in[14];
    const float* bl3 = (const float*)d_in[15];
    const float* Wr3 = (const float*)d_in[16];
    const float* We1 = (const float*)d_in[17];
    const float* be1 = (const float*)d_in[18];
    const float* We2 = (const float*)d_in[19];
    const float* be2 = (const float*)d_in[20];

    float* out    = (float*)d_out;
    float* z      = out;
    float* outpos = out + (size_t)N_NODES * OUT_C;
    float* outneg = outpos + N_POS;

    float *y, *hA, *hB, *wt;
    int* cnt;
    cudaGetSymbolAddress((void**)&y, g_y);
    cudaGetSymbolAddress((void**)&hA, g_hA);
    cudaGetSymbolAddress((void**)&hB, g_hB);
    cudaGetSymbolAddress((void**)&wt, g_wt);
    cudaGetSymbolAddress((void**)&cnt, g_count);
    float* wt1 = wt;
    float* wt2 = wt + 1 * 256 * 128;
    float* wt3 = wt + 2 * 256 * 128;
    float* wt4 = wt + 3 * 256 * 128;

    const int SM128 = (2 * 128 * 36 + 128 * 132) * 4;  // 104448
    const int SM64  = (2 * 128 * 36 + 128 * 68) * 4;   //  71680
    cudaFuncSetAttribute(k_mma<128>, cudaFuncAttributeMaxDynamicSharedMemorySize, SM128);
    cudaFuncSetAttribute(k_mma<64>,  cudaFuncAttributeMaxDynamicSharedMemorySize, SM64);

    const int EB = (N_EDGES + 255) / 256;
    const int SCAN_NB = (N_NODES + 1023) / 1024;
    const int GT = (N_NODES + 127) / 128;
    const int AGGB = (N_NODES * 32 + 255) / 256;

    // ---- CSR build + all weight preps upfront ----
    cudaMemsetAsync(cnt, 0, N_NODES * sizeof(int), 0);
    k_count<<<EB, 256>>>(ei + N_EDGES);
    k_prep<<<(2 * 128 * 128 + 255) / 256, 256>>>(Wl1, Wr1, wt1, 128, 128);
    k_prep<<<(2 * 128 * 128 + 255) / 256, 256>>>(Wl2, Wr2, wt2, 128, 128);
    k_prep<<<(2 * 64 * 128 + 255) / 256, 256>>>(Wl3, Wr3, wt3, 128, 64);
    k_prep<<<(2 * 128 * 64 + 255) / 256, 256>>>(We1, We1 + 64 * 128, wt4, 64, 128);
    k_scan1<<<SCAN_NB, 1024>>>();
    k_scan2<<<1, 32>>>(SCAN_NB);
    k_scan3<<<SCAN_NB, 1024>>>();
    k_fill<<<EB, 256>>>(ei, ei + N_EDGES);

    dim3 gA(GT, 2);   // NOUT=256
    dim3 gB(GT, 1);   // NOUT=128

    // ---- layer 1 ----
    k_mma<128><<<gA, 256, SM128>>>(x, wt1, y, N_NODES, 256);
    k_aggw<128, 256, true><<<AGGB, 256>>>(bl1, g1, b1, x, hA, y);

    // ---- layer 2 ----
    k_mma<128><<<gA, 256, SM128>>>(hA, wt2, y, N_NODES, 256);
    k_aggw<128, 256, true><<<AGGB, 256>>>(bl2, g2, b2, hA, hB, y);

    // ---- layer 3 ----
    k_mma<128><<<gB, 256, SM128>>>(hB, wt3, y, N_NODES, 128);
    k_aggw<64, 128, false><<<AGGB, 256>>>(bl3, nullptr, nullptr, nullptr, z, y);

    // ---- decode prep: y[:,0:128]=P, y[:,128:256]=Q ----
    k_mma<64><<<gA, 256, SM64>>>(z, wt4, y, N_NODES, 256);

    // ---- decode ----
    k_decode<<<(N_POS * 32 + 127) / 128, 128>>>(pos, pos + N_POS, N_POS, be1, We2, be2, outpos, y);
    k_decode<<<(N_NEG * 32 + 127) / 128, 128>>>(neg, neg + N_NEG, N_NEG, be1, We2, be2, outneg, y);
}

// round 6
// speedup vs baseline: 1.1388x; 1.1388x over previous
#include <cuda_runtime.h>
#include <cuda_fp16.h>
#include <cstdint>
#include <cstddef>
#include <math.h>

#define N_NODES 100000
#define N_EDGES 1600000
#define N_POS   200000
#define N_NEG   200000
#define IN_C    128
#define HID_C   128
#define OUT_C   64
#define BN_EPS  1e-5f

// ---------------- scratch (static device globals; no allocation) ----------------
__device__ __half g_yh[N_NODES * 256];    // gathered features (fp16): yl / P|Q
__device__ float  g_yr[N_NODES * 128];    // root-transform features (fp32, read once)
__device__ float  g_hA[N_NODES * HID_C];  // hidden after layer 1
__device__ float  g_hB[N_NODES * HID_C];  // hidden after layer 2
__device__ float  g_wt[4 * 256 * 128];    // 4 pre-rounded weight panels
__device__ int    g_count[N_NODES];
__device__ int    g_off[N_NODES];
__device__ int    g_cur[N_NODES];
__device__ int    g_part[256];
__device__ int    g_srcs[N_EDGES];

// tf32 round-to-nearest
__device__ __forceinline__ uint32_t f2tf32(float f) {
    uint32_t r;
    asm("cvt.rna.tf32.f32 %0, %1;" : "=r"(r) : "f"(f));
    return r;
}

// ---------------- CSR build ----------------
__global__ void k_count(const int* __restrict__ dst) {
    int i = blockIdx.x * blockDim.x + threadIdx.x;
    if (i < N_EDGES) atomicAdd(&g_count[dst[i]], 1);
}
__global__ void k_scan1() {
    __shared__ int sm[1024];
    int i = blockIdx.x * 1024 + threadIdx.x;
    int v = (i < N_NODES) ? g_count[i] : 0;
    sm[threadIdx.x] = v;
    __syncthreads();
    #pragma unroll
    for (int s = 1; s < 1024; s <<= 1) {
        int t = (threadIdx.x >= s) ? sm[threadIdx.x - s] : 0;
        __syncthreads();
        sm[threadIdx.x] += t;
        __syncthreads();
    }
    if (i < N_NODES) g_off[i] = sm[threadIdx.x] - v;
    if (threadIdx.x == 1023) g_part[blockIdx.x] = sm[1023];
}
__global__ void k_scan2(int nb) {
    if (threadIdx.x == 0 && blockIdx.x == 0) {
        int run = 0;
        for (int j = 0; j < nb; j++) { int t = g_part[j]; g_part[j] = run; run += t; }
    }
}
__global__ void k_scan3() {
    int i = blockIdx.x * 1024 + threadIdx.x;
    if (i < N_NODES) {
        int o = g_off[i] + g_part[blockIdx.x];
        g_off[i] = o;
        g_cur[i] = o;
    }
}
__global__ void k_fill(const int* __restrict__ src, const int* __restrict__ dst) {
    int i = blockIdx.x * blockDim.x + threadIdx.x;
    if (i < N_EDGES) {
        int d = dst[i];
        int p = atomicAdd(&g_cur[d], 1);
        g_srcs[p] = src[i];
    }
}

// -------- weight prep: Wt[2*Mh, K] tf32-rounded; rows 0:Mh = s1^T, Mh: = s2^T ----
__global__ void k_prep(const float* __restrict__ s1, const float* __restrict__ s2,
                       float* __restrict__ wt, int K, int Mh) {
    int i = blockIdx.x * 256 + threadIdx.x;
    int tot = 2 * Mh * K;
    if (i >= tot) return;
    int m = i / K, k = i % K;
    float v = (m < Mh) ? s1[(size_t)k * Mh + m] : s2[(size_t)k * Mh + (m - Mh)];
    wt[i] = __uint_as_float(f2tf32(v));
}

// ---------------- tf32 mma.sync GEMM, split fp16/fp32 epilogue ----------------
// C[Nrows, NOUT] = A[Nrows, K] @ Wt[NOUT, K]^T.
// cols < SPLIT -> outH (half, stride SH); cols >= SPLIT -> outF (float, stride SF).
template<int K>
__global__ __launch_bounds__(256, 2) void k_mma(const float* __restrict__ A,
                                                const float* __restrict__ Wt,
                                                __half* __restrict__ outH, int SH, int SPLIT,
                                                float* __restrict__ outF, int SF,
                                                int Nrows) {
    constexpr int CH   = K / 32;
    constexpr int BSTR = K + 4;
    constexpr int K4   = K / 4;
    extern __shared__ float sm[];
    float* As = sm;                       // [2][128][36]
    float* Bs = sm + 2 * 128 * 36;        // [128][BSTR]

    const int tid  = threadIdx.x;
    const int lane = tid & 31, wid = tid >> 5;
    const int gid  = lane >> 2, tg = lane & 3;
    const int mrow = (wid & 3) * 32;
    const int ncol = (wid >> 2) * 64;
    const int row0 = blockIdx.x * 128;
    const int col0 = blockIdx.y * 128;

    // stage whole B panel (pre-rounded tf32 bits, plain copy)
    #pragma unroll
    for (int l = 0; l < K4 / 2; l++) {
        int f = tid + l * 256;
        int r = f / K4, c4 = f % K4;
        float4 v = *(const float4*)(Wt + (size_t)(col0 + r) * K + c4 * 4);
        *(float4*)&Bs[r * BSTR + c4 * 4] = v;
    }

    float4 ra[4];
    #pragma unroll
    for (int l = 0; l < 4; l++) {
        int f = tid + l * 256;
        int r = f >> 3, c4 = f & 7;
        int grow = row0 + r;
        ra[l] = make_float4(0.f, 0.f, 0.f, 0.f);
        if (grow < Nrows) ra[l] = *(const float4*)(A + (size_t)grow * K + c4 * 4);
    }
    #pragma unroll
    for (int l = 0; l < 4; l++) {
        int f = tid + l * 256;
        int r = f >> 3, c4 = f & 7;
        float4 t;
        t.x = __uint_as_float(f2tf32(ra[l].x));
        t.y = __uint_as_float(f2tf32(ra[l].y));
        t.z = __uint_as_float(f2tf32(ra[l].z));
        t.w = __uint_as_float(f2tf32(ra[l].w));
        *(float4*)&As[r * 36 + c4 * 4] = t;
    }
    __syncthreads();

    float c[2][8][4];
    #pragma unroll
    for (int mt = 0; mt < 2; mt++)
        #pragma unroll
        for (int nt = 0; nt < 8; nt++)
            #pragma unroll
            for (int j = 0; j < 4; j++) c[mt][nt][j] = 0.f;

    #pragma unroll
    for (int ch = 0; ch < CH; ch++) {
        if (ch + 1 < CH) {
            #pragma unroll
            for (int l = 0; l < 4; l++) {
                int f = tid + l * 256;
                int r = f >> 3, c4 = f & 7;
                int grow = row0 + r;
                ra[l] = make_float4(0.f, 0.f, 0.f, 0.f);
                if (grow < Nrows)
                    ra[l] = *(const float4*)(A + (size_t)grow * K + (ch + 1) * 32 + c4 * 4);
            }
        }
        const float* Ab = As + (ch & 1) * (128 * 36);
        const int kofs = ch * 32;

        #pragma unroll
        for (int ks = 0; ks < 4; ks++) {
            uint32_t a[2][4];
            #pragma unroll
            for (int mt = 0; mt < 2; mt++) {
                int r = mrow + mt * 16 + gid;
                a[mt][0] = __float_as_uint(Ab[r * 36 + ks * 8 + tg]);
                a[mt][1] = __float_as_uint(Ab[(r + 8) * 36 + ks * 8 + tg]);
                a[mt][2] = __float_as_uint(Ab[r * 36 + ks * 8 + tg + 4]);
                a[mt][3] = __float_as_uint(Ab[(r + 8) * 36 + ks * 8 + tg + 4]);
            }
            uint32_t b[8][2];
            #pragma unroll
            for (int nt = 0; nt < 8; nt++) {
                int rn = ncol + nt * 8 + gid;
                b[nt][0] = __float_as_uint(Bs[rn * BSTR + kofs + ks * 8 + tg]);
                b[nt][1] = __float_as_uint(Bs[rn * BSTR + kofs + ks * 8 + tg + 4]);
            }
            #pragma unroll
            for (int mt = 0; mt < 2; mt++)
                #pragma unroll
                for (int nt = 0; nt < 8; nt++)
                    asm volatile(
                        "mma.sync.aligned.m16n8k8.row.col.f32.tf32.tf32.f32 "
                        "{%0,%1,%2,%3}, {%4,%5,%6,%7}, {%8,%9}, {%0,%1,%2,%3};"
                        : "+f"(c[mt][nt][0]), "+f"(c[mt][nt][1]),
                          "+f"(c[mt][nt][2]), "+f"(c[mt][nt][3])
                        : "r"(a[mt][0]), "r"(a[mt][1]), "r"(a[mt][2]), "r"(a[mt][3]),
                          "r"(b[nt][0]), "r"(b[nt][1]));
        }

        if (ch + 1 < CH) {
            float* An = As + ((ch + 1) & 1) * (128 * 36);
            #pragma unroll
            for (int l = 0; l < 4; l++) {
                int f = tid + l * 256;
                int r = f >> 3, c4 = f & 7;
                float4 t;
                t.x = __uint_as_float(f2tf32(ra[l].x));
                t.y = __uint_as_float(f2tf32(ra[l].y));
                t.z = __uint_as_float(f2tf32(ra[l].z));
                t.w = __uint_as_float(f2tf32(ra[l].w));
                *(float4*)&An[r * 36 + c4 * 4] = t;
            }
            __syncthreads();
        }
    }

    // epilogue: pairs (c0,c1)@r0, (c2,c3)@r1 at column colg..colg+1
    #pragma unroll
    for (int mt = 0; mt < 2; mt++) {
        int r0 = row0 + mrow + mt * 16 + gid;
        int r1 = r0 + 8;
        #pragma unroll
        for (int nt = 0; nt < 8; nt++) {
            int colg = col0 + ncol + nt * 8 + 2 * tg;
            if (colg < SPLIT) {
                if (r0 < Nrows)
                    *(__half2*)(outH + (size_t)r0 * SH + colg) =
                        __halves2half2(__float2half_rn(c[mt][nt][0]), __float2half_rn(c[mt][nt][1]));
                if (r1 < Nrows)
                    *(__half2*)(outH + (size_t)r1 * SH + colg) =
                        __halves2half2(__float2half_rn(c[mt][nt][2]), __float2half_rn(c[mt][nt][3]));
            } else {
                int cf = colg - SPLIT;
                if (r0 < Nrows)
                    *(float2*)(outF + (size_t)r0 * SF + cf) = make_float2(c[mt][nt][0], c[mt][nt][1]);
                if (r1 < Nrows)
                    *(float2*)(outF + (size_t)r1 * SF + cf) = make_float2(c[mt][nt][2], c[mt][nt][3]);
            }
        }
    }
}

// ---------------- fused aggregation + combine (warp per node, fp16 gather) ------
template<int C, bool FULL>
__global__ __launch_bounds__(256) void k_aggh(const float* __restrict__ bl,
                                              const float* __restrict__ gam,
                                              const float* __restrict__ bet,
                                              const float* __restrict__ h_in,
                                              float* __restrict__ h_out,
                                              const __half* __restrict__ yh,
                                              const float* __restrict__ yr) {
    constexpr int V = C / 32;   // channels per lane: 4 (C=128) or 2 (C=64)
    int warp = (blockIdx.x * 256 + threadIdx.x) >> 5;
    int lane = threadIdx.x & 31;
    if (warp >= N_NODES) return;
    int n = warp;
    int beg = g_off[n], cnt = g_count[n];

    float acc[V];
    #pragma unroll
    for (int j = 0; j < V; j++) acc[j] = 0.f;

    for (int e0 = 0; e0 < cnt; e0 += 32) {
        int m = min(32, cnt - e0);
        int myidx = (lane < m) ? __ldg(&g_srcs[beg + e0 + lane]) : 0;
        int i = 0;
        for (; i + 4 <= m; i += 4) {
            int s0 = __shfl_sync(0xFFFFFFFFu, myidx, i);
            int s1 = __shfl_sync(0xFFFFFFFFu, myidx, i + 1);
            int s2 = __shfl_sync(0xFFFFFFFFu, myidx, i + 2);
            int s3 = __shfl_sync(0xFFFFFFFFu, myidx, i + 3);
            if (V == 4) {
                uint2 u0 = *(const uint2*)(yh + (size_t)s0 * C + lane * 4);
                uint2 u1 = *(const uint2*)(yh + (size_t)s1 * C + lane * 4);
                uint2 u2 = *(const uint2*)(yh + (size_t)s2 * C + lane * 4);
                uint2 u3 = *(const uint2*)(yh + (size_t)s3 * C + lane * 4);
                float2 a0 = __half22float2(*(__half2*)&u0.x), b0 = __half22float2(*(__half2*)&u0.y);
                float2 a1 = __half22float2(*(__half2*)&u1.x), b1 = __half22float2(*(__half2*)&u1.y);
                float2 a2 = __half22float2(*(__half2*)&u2.x), b2 = __half22float2(*(__half2*)&u2.y);
                float2 a3 = __half22float2(*(__half2*)&u3.x), b3 = __half22float2(*(__half2*)&u3.y);
                acc[0] += a0.x + a1.x + a2.x + a3.x;
                acc[1] += a0.y + a1.y + a2.y + a3.y;
                acc[2] += b0.x + b1.x + b2.x + b3.x;
                acc[3] += b0.y + b1.y + b2.y + b3.y;
            } else {
                uint32_t u0 = *(const uint32_t*)(yh + (size_t)s0 * C + lane * 2);
                uint32_t u1 = *(const uint32_t*)(yh + (size_t)s1 * C + lane * 2);
                uint32_t u2 = *(const uint32_t*)(yh + (size_t)s2 * C + lane * 2);
                uint32_t u3 = *(const uint32_t*)(yh + (size_t)s3 * C + lane * 2);
                float2 a0 = __half22float2(*(__half2*)&u0);
                float2 a1 = __half22float2(*(__half2*)&u1);
                float2 a2 = __half22float2(*(__half2*)&u2);
                float2 a3 = __half22float2(*(__half2*)&u3);
                acc[0] += a0.x + a1.x + a2.x + a3.x;
                acc[1] += a0.y + a1.y + a2.y + a3.y;
            }
        }
        for (; i < m; i++) {
            int s = __shfl_sync(0xFFFFFFFFu, myidx, i);
            if (V == 4) {
                uint2 u = *(const uint2*)(yh + (size_t)s * C + lane * 4);
                float2 a = __half22float2(*(__half2*)&u.x), b = __half22float2(*(__half2*)&u.y);
                acc[0] += a.x; acc[1] += a.y; acc[2] += b.x; acc[3] += b.y;
            } else {
                uint32_t u = *(const uint32_t*)(yh + (size_t)s * C + lane * 2);
                float2 a = __half22float2(*(__half2*)&u);
                acc[0] += a.x; acc[1] += a.y;
            }
        }
    }
    float inv = 1.0f / fmaxf((float)cnt, 1.0f);

    float o[V];
    {
        const float* rr = yr + (size_t)n * C + lane * V;
        #pragma unroll
        for (int j = 0; j < V; j++)
            o[j] = acc[j] * inv + bl[lane * V + j] + rr[j];
    }
    if (FULL) {
        const float s = rsqrtf(1.0f + BN_EPS);
        const float* hp = h_in + (size_t)n * C + lane * V;
        #pragma unroll
        for (int j = 0; j < V; j++) {
            int ch = lane * V + j;
            o[j] = fmaxf(o[j] * (gam[ch] * s) + bet[ch], 0.f) + hp[j];
        }
    }
    float* op = h_out + (size_t)n * C + lane * V;
    if (V == 4) *(float4*)op = make_float4(o[0], o[1], o[2], o[V - 1]);
    else        *(float2*)op = make_float2(o[0], o[1]);
}

// ---------------- edge decode: sigmoid(relu(P[s]+Q[d]+be1) . We2 + be2) --------
__global__ void k_decode(const int* __restrict__ sidx, const int* __restrict__ didx, int E,
                         const float* __restrict__ be1,
                         const float* __restrict__ We2, const float* __restrict__ be2,
                         float* __restrict__ out, const __half* __restrict__ yh) {
    int warp = (blockIdx.x * blockDim.x + threadIdx.x) >> 5;
    int lane = threadIdx.x & 31;
    if (warp >= E) return;
    int s = sidx[warp], d = didx[warp];
    uint2 up = *(const uint2*)(yh + (size_t)s * 256 + lane * 4);
    uint2 uq = *(const uint2*)(yh + (size_t)d * 256 + 128 + lane * 4);
    float2 p0 = __half22float2(*(__half2*)&up.x), p1 = __half22float2(*(__half2*)&up.y);
    float2 q0 = __half22float2(*(__half2*)&uq.x), q1 = __half22float2(*(__half2*)&uq.y);
    float4 bb = *(const float4*)(be1 + lane * 4);
    float4 w  = *(const float4*)(We2 + lane * 4);
    float sum = fmaxf(p0.x + q0.x + bb.x, 0.f) * w.x
              + fmaxf(p0.y + q0.y + bb.y, 0.f) * w.y
              + fmaxf(p1.x + q1.x + bb.z, 0.f) * w.z
              + fmaxf(p1.y + q1.y + bb.w, 0.f) * w.w;
    #pragma unroll
    for (int o = 16; o; o >>= 1) sum += __shfl_xor_sync(0xFFFFFFFFu, sum, o);
    if (lane == 0) out[warp] = 1.0f / (1.0f + expf(-(sum + be2[0])));
}

// ---------------- host launcher ----------------
extern "C" void kernel_launch(void* const* d_in, const int* in_sizes, int n_in,
                              void* d_out, int out_size) {
    const float* x   = (const float*)d_in[0];
    const int*   ei  = (const int*)d_in[1];
    const int*   pos = (const int*)d_in[2];
    const int*   neg = (const int*)d_in[3];
    const float* Wl1 = (const float*)d_in[4];
    const float* bl1 = (const float*)d_in[5];
    const float* Wr1 = (const float*)d_in[6];
    const float* g1  = (const float*)d_in[7];
    const float* b1  = (const float*)d_in[8];
    const float* Wl2 = (const float*)d_in[9];
    const float* bl2 = (const float*)d_in[10];
    const float* Wr2 = (const float*)d_in[11];
    const float* g2  = (const float*)d_in[12];
    const float* b2  = (const float*)d_in[13];
    const float* Wl3 = (const float*)d_in[14];
    const float* bl3 = (const float*)d_in[15];
    const float* Wr3 = (const float*)d_in[16];
    const float* We1 = (const float*)d_in[17];
    const float* be1 = (const float*)d_in[18];
    const float* We2 = (const float*)d_in[19];
    const float* be2 = (const float*)d_in[20];

    float* out    = (float*)d_out;
    float* z      = out;
    float* outpos = out + (size_t)N_NODES * OUT_C;
    float* outneg = outpos + N_POS;

    __half* yh;
    float *yr, *hA, *hB, *wt;
    int* cnt;
    cudaGetSymbolAddress((void**)&yh, g_yh);
    cudaGetSymbolAddress((void**)&yr, g_yr);
    cudaGetSymbolAddress((void**)&hA, g_hA);
    cudaGetSymbolAddress((void**)&hB, g_hB);
    cudaGetSymbolAddress((void**)&wt, g_wt);
    cudaGetSymbolAddress((void**)&cnt, g_count);
    float* wt1 = wt;
    float* wt2 = wt + 1 * 256 * 128;
    float* wt3 = wt + 2 * 256 * 128;
    float* wt4 = wt + 3 * 256 * 128;

    const int SM128 = (2 * 128 * 36 + 128 * 132) * 4;  // 104448
    const int SM64  = (2 * 128 * 36 + 128 * 68) * 4;   //  71680
    cudaFuncSetAttribute(k_mma<128>, cudaFuncAttributeMaxDynamicSharedMemorySize, SM128);
    cudaFuncSetAttribute(k_mma<64>,  cudaFuncAttributeMaxDynamicSharedMemorySize, SM64);

    const int EB = (N_EDGES + 255) / 256;
    const int SCAN_NB = (N_NODES + 1023) / 1024;
    const int GT = (N_NODES + 127) / 128;
    const int AGGB = (N_NODES * 32 + 255) / 256;

    // ---- CSR build + all weight preps upfront ----
    cudaMemsetAsync(cnt, 0, N_NODES * sizeof(int), 0);
    k_count<<<EB, 256>>>(ei + N_EDGES);
    k_prep<<<(2 * 128 * 128 + 255) / 256, 256>>>(Wl1, Wr1, wt1, 128, 128);
    k_prep<<<(2 * 128 * 128 + 255) / 256, 256>>>(Wl2, Wr2, wt2, 128, 128);
    k_prep<<<(2 * 64 * 128 + 255) / 256, 256>>>(Wl3, Wr3, wt3, 128, 64);
    k_prep<<<(2 * 128 * 64 + 255) / 256, 256>>>(We1, We1 + 64 * 128, wt4, 64, 128);
    k_scan1<<<SCAN_NB, 1024>>>();
    k_scan2<<<1, 32>>>(SCAN_NB);
    k_scan3<<<SCAN_NB, 1024>>>();
    k_fill<<<EB, 256>>>(ei, ei + N_EDGES);

    dim3 gA(GT, 2);   // NOUT=256
    dim3 gB(GT, 1);   // NOUT=128

    // ---- layer 1: yl(cols<128)->half, yr(cols>=128)->fp32 ----
    k_mma<128><<<gA, 256, SM128>>>(x, wt1, yh, 128, 128, yr, 128, N_NODES);
    k_aggh<128, true><<<AGGB, 256>>>(bl1, g1, b1, x, hA, yh, yr);

    // ---- layer 2 ----
    k_mma<128><<<gA, 256, SM128>>>(hA, wt2, yh, 128, 128, yr, 128, N_NODES);
    k_aggh<128, true><<<AGGB, 256>>>(bl2, g2, b2, hA, hB, yh, yr);

    // ---- layer 3 (C=64) ----
    k_mma<128><<<gB, 256, SM128>>>(hB, wt3, yh, 64, 64, yr, 64, N_NODES);
    k_aggh<64, false><<<AGGB, 256>>>(bl3, nullptr, nullptr, nullptr, z, yh, yr);

    // ---- decode prep: yh[n][0:128]=P, yh[n][128:256]=Q (all half) ----
    k_mma<64><<<gA, 256, SM64>>>(z, wt4, yh, 256, 256, nullptr, 0, N_NODES);

    // ---- decode ----
    k_decode<<<(N_POS * 32 + 127) / 128, 128>>>(pos, pos + N_POS, N_POS, be1, We2, be2, outpos, yh);
    k_decode<<<(N_NEG * 32 + 127) / 128, 128>>>(neg, neg + N_NEG, N_NEG, be1, We2, be2, outneg, yh);
}

// round 7
// speedup vs baseline: 1.3013x; 1.1427x over previous
#include <cuda_runtime.h>
#include <cuda_fp16.h>
#include <cstdint>
#include <cstddef>
#include <math.h>

#define N_NODES 100000
#define N_EDGES 1600000
#define N_POS   200000
#define N_NEG   200000
#define IN_C    128
#define HID_C   128
#define OUT_C   64
#define BN_EPS  1e-5f

// ---------------- scratch (static device globals; no allocation) ----------------
__device__ __half g_yh[N_NODES * 256];    // gathered features (fp16): yl / P|Q
__device__ float  g_yr[N_NODES * 128];    // root-transform features (fp32, read once)
__device__ float  g_hA[N_NODES * HID_C];  // hidden after layer 1
__device__ float  g_hB[N_NODES * HID_C];  // hidden after layer 2
__device__ __half g_wth[4 * 256 * 128];   // 4 fp16 weight panels (transposed+fused)
__device__ int    g_count[N_NODES];
__device__ int    g_off[N_NODES];
__device__ int    g_cur[N_NODES];
__device__ int    g_part[256];
__device__ int    g_srcs[N_EDGES];

// ---------------- CSR build ----------------
__global__ void k_count(const int* __restrict__ dst) {
    int i = blockIdx.x * blockDim.x + threadIdx.x;
    if (i < N_EDGES) atomicAdd(&g_count[dst[i]], 1);
}
__global__ void k_scan1() {
    __shared__ int sm[1024];
    int i = blockIdx.x * 1024 + threadIdx.x;
    int v = (i < N_NODES) ? g_count[i] : 0;
    sm[threadIdx.x] = v;
    __syncthreads();
    #pragma unroll
    for (int s = 1; s < 1024; s <<= 1) {
        int t = (threadIdx.x >= s) ? sm[threadIdx.x - s] : 0;
        __syncthreads();
        sm[threadIdx.x] += t;
        __syncthreads();
    }
    if (i < N_NODES) g_off[i] = sm[threadIdx.x] - v;
    if (threadIdx.x == 1023) g_part[blockIdx.x] = sm[1023];
}
__global__ void k_scan2(int nb) {
    if (threadIdx.x == 0 && blockIdx.x == 0) {
        int run = 0;
        for (int j = 0; j < nb; j++) { int t = g_part[j]; g_part[j] = run; run += t; }
    }
}
__global__ void k_scan3() {
    int i = blockIdx.x * 1024 + threadIdx.x;
    if (i < N_NODES) {
        int o = g_off[i] + g_part[blockIdx.x];
        g_off[i] = o;
        g_cur[i] = o;
    }
}
__global__ void k_fill(const int* __restrict__ src, const int* __restrict__ dst) {
    int i = blockIdx.x * blockDim.x + threadIdx.x;
    if (i < N_EDGES) {
        int d = dst[i];
        int p = atomicAdd(&g_cur[d], 1);
        g_srcs[p] = src[i];
    }
}

// -------- weight prep: Wt[2*Mh, K] fp16; rows 0:Mh = s1^T, Mh: = s2^T ----
__global__ void k_prep(const float* __restrict__ s1, const float* __restrict__ s2,
                       __half* __restrict__ wt, int K, int Mh) {
    int i = blockIdx.x * 256 + threadIdx.x;
    int tot = 2 * Mh * K;
    if (i >= tot) return;
    int m = i / K, k = i % K;
    float v = (m < Mh) ? s1[(size_t)k * Mh + m] : s2[(size_t)k * Mh + (m - Mh)];
    wt[i] = __float2half_rn(v);
}

// ---------------- fp16 mma.sync m16n8k16 GEMM, split fp16/fp32 epilogue ----------
// C[Nrows, NOUT] = A[Nrows, K] @ Wt[NOUT, K]^T, fp32 accumulate.
// CTA 128 rows x 128 cols (grid.y panels). Whole-K tiles staged once.
// cols < SPLIT -> outH (half, stride SH); cols >= SPLIT -> outF (float, stride SF).
template<int K>
__global__ __launch_bounds__(256, 2) void k_mma(const float* __restrict__ A,
                                                const __half* __restrict__ Wt,
                                                __half* __restrict__ outH, int SH, int SPLIT,
                                                float* __restrict__ outF, int SF,
                                                int Nrows) {
    constexpr int SA = K + 8;            // halves per row (stride)
    extern __shared__ __half sh[];
    __half* As = sh;                     // [128][SA]
    __half* Bs = sh + 128 * SA;          // [128][SA]

    const int tid  = threadIdx.x;
    const int lane = tid & 31, wid = tid >> 5;
    const int gid  = lane >> 2, tg = lane & 3;
    const int mrow = (wid & 3) * 32;
    const int ncol = (wid >> 2) * 64;
    const int row0 = blockIdx.x * 128;
    const int col0 = blockIdx.y * 128;

    // stage A: 128 x K floats -> half. 128*(K/4) float4 total, K/8 per thread.
    #pragma unroll
    for (int l = 0; l < K / 8; l++) {
        int f = tid + l * 256;
        int r = f / (K / 4), c4 = f % (K / 4);
        int grow = row0 + r;
        float4 v = make_float4(0.f, 0.f, 0.f, 0.f);
        if (grow < Nrows) v = *(const float4*)(A + (size_t)grow * K + c4 * 4);
        __half2 h0 = __floats2half2_rn(v.x, v.y);
        __half2 h1 = __floats2half2_rn(v.z, v.w);
        uint2 u;
        u.x = *(uint32_t*)&h0;
        u.y = *(uint32_t*)&h1;
        *(uint2*)(As + r * SA + c4 * 4) = u;
    }
    // stage B: 128 x K halves, pure copy. 128*(K/8) uint4 total, K/16 per thread.
    #pragma unroll
    for (int l = 0; l < K / 16; l++) {
        int f = tid + l * 256;
        int r = f / (K / 8), c8 = f % (K / 8);
        uint4 v = *(const uint4*)(Wt + (size_t)(col0 + r) * K + c8 * 8);
        *(uint4*)(Bs + r * SA + c8 * 8) = v;
    }
    __syncthreads();

    float c[2][8][4];
    #pragma unroll
    for (int mt = 0; mt < 2; mt++)
        #pragma unroll
        for (int nt = 0; nt < 8; nt++)
            #pragma unroll
            for (int j = 0; j < 4; j++) c[mt][nt][j] = 0.f;

    #pragma unroll
    for (int ks = 0; ks < K / 16; ks++) {
        const int k0 = ks * 16;
        uint32_t a[2][4];
        #pragma unroll
        for (int mt = 0; mt < 2; mt++) {
            int r = mrow + mt * 16 + gid;
            a[mt][0] = *(const uint32_t*)(As + r * SA + k0 + 2 * tg);
            a[mt][1] = *(const uint32_t*)(As + (r + 8) * SA + k0 + 2 * tg);
            a[mt][2] = *(const uint32_t*)(As + r * SA + k0 + 8 + 2 * tg);
            a[mt][3] = *(const uint32_t*)(As + (r + 8) * SA + k0 + 8 + 2 * tg);
        }
        uint32_t b[8][2];
        #pragma unroll
        for (int nt = 0; nt < 8; nt++) {
            int rn = ncol + nt * 8 + gid;
            b[nt][0] = *(const uint32_t*)(Bs + rn * SA + k0 + 2 * tg);
            b[nt][1] = *(const uint32_t*)(Bs + rn * SA + k0 + 8 + 2 * tg);
        }
        #pragma unroll
        for (int mt = 0; mt < 2; mt++)
            #pragma unroll
            for (int nt = 0; nt < 8; nt++)
                asm volatile(
                    "mma.sync.aligned.m16n8k16.row.col.f32.f16.f16.f32 "
                    "{%0,%1,%2,%3}, {%4,%5,%6,%7}, {%8,%9}, {%0,%1,%2,%3};"
                    : "+f"(c[mt][nt][0]), "+f"(c[mt][nt][1]),
                      "+f"(c[mt][nt][2]), "+f"(c[mt][nt][3])
                    : "r"(a[mt][0]), "r"(a[mt][1]), "r"(a[mt][2]), "r"(a[mt][3]),
                      "r"(b[nt][0]), "r"(b[nt][1]));
    }

    // epilogue: (c0,c1)@r0, (c2,c3)@r1, columns colg, colg+1
    #pragma unroll
    for (int mt = 0; mt < 2; mt++) {
        int r0 = row0 + mrow + mt * 16 + gid;
        int r1 = r0 + 8;
        #pragma unroll
        for (int nt = 0; nt < 8; nt++) {
            int colg = col0 + ncol + nt * 8 + 2 * tg;
            if (colg < SPLIT) {
                if (r0 < Nrows)
                    *(__half2*)(outH + (size_t)r0 * SH + colg) =
                        __halves2half2(__float2half_rn(c[mt][nt][0]), __float2half_rn(c[mt][nt][1]));
                if (r1 < Nrows)
                    *(__half2*)(outH + (size_t)r1 * SH + colg) =
                        __halves2half2(__float2half_rn(c[mt][nt][2]), __float2half_rn(c[mt][nt][3]));
            } else {
                int cf = colg - SPLIT;
                if (r0 < Nrows)
                    *(float2*)(outF + (size_t)r0 * SF + cf) = make_float2(c[mt][nt][0], c[mt][nt][1]);
                if (r1 < Nrows)
                    *(float2*)(outF + (size_t)r1 * SF + cf) = make_float2(c[mt][nt][2], c[mt][nt][3]);
            }
        }
    }
}

// ---------------- fused aggregation + combine (warp per node, fp16 gather) ------
template<int C, bool FULL>
__global__ __launch_bounds__(256) void k_aggh(const float* __restrict__ bl,
                                              const float* __restrict__ gam,
                                              const float* __restrict__ bet,
                                              const float* __restrict__ h_in,
                                              float* __restrict__ h_out,
                                              const __half* __restrict__ yh,
                                              const float* __restrict__ yr) {
    constexpr int V = C / 32;   // channels per lane: 4 (C=128) or 2 (C=64)
    int warp = (blockIdx.x * 256 + threadIdx.x) >> 5;
    int lane = threadIdx.x & 31;
    if (warp >= N_NODES) return;
    int n = warp;
    int beg = g_off[n], cnt = g_count[n];

    float acc[V];
    #pragma unroll
    for (int j = 0; j < V; j++) acc[j] = 0.f;

    for (int e0 = 0; e0 < cnt; e0 += 32) {
        int m = min(32, cnt - e0);
        int myidx = (lane < m) ? __ldg(&g_srcs[beg + e0 + lane]) : 0;
        int i = 0;
        for (; i + 4 <= m; i += 4) {
            int s0 = __shfl_sync(0xFFFFFFFFu, myidx, i);
            int s1 = __shfl_sync(0xFFFFFFFFu, myidx, i + 1);
            int s2 = __shfl_sync(0xFFFFFFFFu, myidx, i + 2);
            int s3 = __shfl_sync(0xFFFFFFFFu, myidx, i + 3);
            if (V == 4) {
                uint2 u0 = *(const uint2*)(yh + (size_t)s0 * C + lane * 4);
                uint2 u1 = *(const uint2*)(yh + (size_t)s1 * C + lane * 4);
                uint2 u2 = *(const uint2*)(yh + (size_t)s2 * C + lane * 4);
                uint2 u3 = *(const uint2*)(yh + (size_t)s3 * C + lane * 4);
                float2 a0 = __half22float2(*(__half2*)&u0.x), b0 = __half22float2(*(__half2*)&u0.y);
                float2 a1 = __half22float2(*(__half2*)&u1.x), b1 = __half22float2(*(__half2*)&u1.y);
                float2 a2 = __half22float2(*(__half2*)&u2.x), b2 = __half22float2(*(__half2*)&u2.y);
                float2 a3 = __half22float2(*(__half2*)&u3.x), b3 = __half22float2(*(__half2*)&u3.y);
                acc[0] += a0.x + a1.x + a2.x + a3.x;
                acc[1] += a0.y + a1.y + a2.y + a3.y;
                acc[2] += b0.x + b1.x + b2.x + b3.x;
                acc[3] += b0.y + b1.y + b2.y + b3.y;
            } else {
                uint32_t u0 = *(const uint32_t*)(yh + (size_t)s0 * C + lane * 2);
                uint32_t u1 = *(const uint32_t*)(yh + (size_t)s1 * C + lane * 2);
                uint32_t u2 = *(const uint32_t*)(yh + (size_t)s2 * C + lane * 2);
                uint32_t u3 = *(const uint32_t*)(yh + (size_t)s3 * C + lane * 2);
                float2 a0 = __half22float2(*(__half2*)&u0);
                float2 a1 = __half22float2(*(__half2*)&u1);
                float2 a2 = __half22float2(*(__half2*)&u2);
                float2 a3 = __half22float2(*(__half2*)&u3);
                acc[0] += a0.x + a1.x + a2.x + a3.x;
                acc[1] += a0.y + a1.y + a2.y + a3.y;
            }
        }
        for (; i < m; i++) {
            int s = __shfl_sync(0xFFFFFFFFu, myidx, i);
            if (V == 4) {
                uint2 u = *(const uint2*)(yh + (size_t)s * C + lane * 4);
                float2 a = __half22float2(*(__half2*)&u.x), b = __half22float2(*(__half2*)&u.y);
                acc[0] += a.x; acc[1] += a.y; acc[2] += b.x; acc[3] += b.y;
            } else {
                uint32_t u = *(const uint32_t*)(yh + (size_t)s * C + lane * 2);
                float2 a = __half22float2(*(__half2*)&u);
                acc[0] += a.x; acc[1] += a.y;
            }
        }
    }
    float inv = 1.0f / fmaxf((float)cnt, 1.0f);

    float o[V];
    {
        const float* rr = yr + (size_t)n * C + lane * V;
        #pragma unroll
        for (int j = 0; j < V; j++)
            o[j] = acc[j] * inv + bl[lane * V + j] + rr[j];
    }
    if (FULL) {
        const float s = rsqrtf(1.0f + BN_EPS);
        const float* hp = h_in + (size_t)n * C + lane * V;
        #pragma unroll
        for (int j = 0; j < V; j++) {
            int ch = lane * V + j;
            o[j] = fmaxf(o[j] * (gam[ch] * s) + bet[ch], 0.f) + hp[j];
        }
    }
    float* op = h_out + (size_t)n * C + lane * V;
    if (V == 4) *(float4*)op = make_float4(o[0], o[1], o[2], o[V - 1]);
    else        *(float2*)op = make_float2(o[0], o[1]);
}

// ---------------- edge decode: sigmoid(relu(P[s]+Q[d]+be1) . We2 + be2) --------
__global__ void k_decode(const int* __restrict__ sidx, const int* __restrict__ didx, int E,
                         const float* __restrict__ be1,
                         const float* __restrict__ We2, const float* __restrict__ be2,
                         float* __restrict__ out, const __half* __restrict__ yh) {
    int warp = (blockIdx.x * blockDim.x + threadIdx.x) >> 5;
    int lane = threadIdx.x & 31;
    if (warp >= E) return;
    int s = sidx[warp], d = didx[warp];
    uint2 up = *(const uint2*)(yh + (size_t)s * 256 + lane * 4);
    uint2 uq = *(const uint2*)(yh + (size_t)d * 256 + 128 + lane * 4);
    float2 p0 = __half22float2(*(__half2*)&up.x), p1 = __half22float2(*(__half2*)&up.y);
    float2 q0 = __half22float2(*(__half2*)&uq.x), q1 = __half22float2(*(__half2*)&uq.y);
    float4 bb = *(const float4*)(be1 + lane * 4);
    float4 w  = *(const float4*)(We2 + lane * 4);
    float sum = fmaxf(p0.x + q0.x + bb.x, 0.f) * w.x
              + fmaxf(p0.y + q0.y + bb.y, 0.f) * w.y
              + fmaxf(p1.x + q1.x + bb.z, 0.f) * w.z
              + fmaxf(p1.y + q1.y + bb.w, 0.f) * w.w;
    #pragma unroll
    for (int o = 16; o; o >>= 1) sum += __shfl_xor_sync(0xFFFFFFFFu, sum, o);
    if (lane == 0) out[warp] = 1.0f / (1.0f + expf(-(sum + be2[0])));
}

// ---------------- host launcher ----------------
extern "C" void kernel_launch(void* const* d_in, const int* in_sizes, int n_in,
                              void* d_out, int out_size) {
    const float* x   = (const float*)d_in[0];
    const int*   ei  = (const int*)d_in[1];
    const int*   pos = (const int*)d_in[2];
    const int*   neg = (const int*)d_in[3];
    const float* Wl1 = (const float*)d_in[4];
    const float* bl1 = (const float*)d_in[5];
    const float* Wr1 = (const float*)d_in[6];
    const float* g1  = (const float*)d_in[7];
    const float* b1  = (const float*)d_in[8];
    const float* Wl2 = (const float*)d_in[9];
    const float* bl2 = (const float*)d_in[10];
    const float* Wr2 = (const float*)d_in[11];
    const float* g2  = (const float*)d_in[12];
    const float* b2  = (const float*)d_in[13];
    const float* Wl3 = (const float*)d_in[14];
    const float* bl3 = (const float*)d_in[15];
    const float* Wr3 = (const float*)d_in[16];
    const float* We1 = (const float*)d_in[17];
    const float* be1 = (const float*)d_in[18];
    const float* We2 = (const float*)d_in[19];
    const float* be2 = (const float*)d_in[20];

    float* out    = (float*)d_out;
    float* z      = out;
    float* outpos = out + (size_t)N_NODES * OUT_C;
    float* outneg = outpos + N_POS;

    __half *yh, *wt;
    float *yr, *hA, *hB;
    int* cnt;
    cudaGetSymbolAddress((void**)&yh, g_yh);
    cudaGetSymbolAddress((void**)&yr, g_yr);
    cudaGetSymbolAddress((void**)&hA, g_hA);
    cudaGetSymbolAddress((void**)&hB, g_hB);
    cudaGetSymbolAddress((void**)&wt, g_wth);
    cudaGetSymbolAddress((void**)&cnt, g_count);
    __half* wt1 = wt;
    __half* wt2 = wt + 1 * 256 * 128;
    __half* wt3 = wt + 2 * 256 * 128;
    __half* wt4 = wt + 3 * 256 * 128;

    const int SM128 = 2 * 128 * (128 + 8) * 2;  // 69632
    const int SM64  = 2 * 128 * (64 + 8) * 2;   // 36864
    cudaFuncSetAttribute(k_mma<128>, cudaFuncAttributeMaxDynamicSharedMemorySize, SM128);
    cudaFuncSetAttribute(k_mma<64>,  cudaFuncAttributeMaxDynamicSharedMemorySize, SM64);

    const int EB = (N_EDGES + 255) / 256;
    const int SCAN_NB = (N_NODES + 1023) / 1024;
    const int GT = (N_NODES + 127) / 128;
    const int AGGB = (N_NODES * 32 + 255) / 256;

    // ---- CSR build + all weight preps upfront ----
    cudaMemsetAsync(cnt, 0, N_NODES * sizeof(int), 0);
    k_count<<<EB, 256>>>(ei + N_EDGES);
    k_prep<<<(2 * 128 * 128 + 255) / 256, 256>>>(Wl1, Wr1, wt1, 128, 128);
    k_prep<<<(2 * 128 * 128 + 255) / 256, 256>>>(Wl2, Wr2, wt2, 128, 128);
    k_prep<<<(2 * 64 * 128 + 255) / 256, 256>>>(Wl3, Wr3, wt3, 128, 64);
    k_prep<<<(2 * 128 * 64 + 255) / 256, 256>>>(We1, We1 + 64 * 128, wt4, 64, 128);
    k_scan1<<<SCAN_NB, 1024>>>();
    k_scan2<<<1, 32>>>(SCAN_NB);
    k_scan3<<<SCAN_NB, 1024>>>();
    k_fill<<<EB, 256>>>(ei, ei + N_EDGES);

    dim3 gA(GT, 2);   // NOUT=256
    dim3 gB(GT, 1);   // NOUT=128

    // ---- layer 1: yl(cols<128)->half, yr(cols>=128)->fp32 ----
    k_mma<128><<<gA, 256, SM128>>>(x, wt1, yh, 128, 128, yr, 128, N_NODES);
    k_aggh<128, true><<<AGGB, 256>>>(bl1, g1, b1, x, hA, yh, yr);

    // ---- layer 2 ----
    k_mma<128><<<gA, 256, SM128>>>(hA, wt2, yh, 128, 128, yr, 128, N_NODES);
    k_aggh<128, true><<<AGGB, 256>>>(bl2, g2, b2, hA, hB, yh, yr);

    // ---- layer 3 (C=64) ----
    k_mma<128><<<gB, 256, SM128>>>(hB, wt3, yh, 64, 64, yr, 64, N_NODES);
    k_aggh<64, false><<<AGGB, 256>>>(bl3, nullptr, nullptr, nullptr, z, yh, yr);

    // ---- decode prep: yh[n][0:128]=P, yh[n][128:256]=Q (all half) ----
    k_mma<64><<<gA, 256, SM64>>>(z, wt4, yh, 256, 256, nullptr, 0, N_NODES);

    // ---- decode ----
    k_decode<<<(N_POS * 32 + 127) / 128, 128>>>(pos, pos + N_POS, N_POS, be1, We2, be2, outpos, yh);
    k_decode<<<(N_NEG * 32 + 127) / 128, 128>>>(neg, neg + N_NEG, N_NEG, be1, We2, be2, outneg, yh);
}

// round 10
// speedup vs baseline: 1.4154x; 1.0877x over previous
#include <cuda_runtime.h>
#include <cuda_fp16.h>
#include <cstdint>
#include <cstddef>
#include <math.h>

#define N_NODES 100000
#define N_EDGES 1600000
#define N_POS   200000
#define N_NEG   200000
#define IN_C    128
#define HID_C   128
#define OUT_C   64
#define BN_EPS  1e-5f

// ---------------- scratch (static device globals; no allocation) ----------------
__device__ __half g_yh[N_NODES * 256];    // gathered features (fp16): yl / P|Q
__device__ __half g_yrh[N_NODES * 128];   // root-transform features (fp16, read once)
__device__ __half g_hA[N_NODES * HID_C];  // hidden after layer 1 (fp16)
__device__ __half g_hB[N_NODES * HID_C];  // hidden after layer 2 (fp16)
__device__ __half g_wth[4 * 256 * 128];   // packed fp16 weight panels
__device__ int    g_count[N_NODES];
__device__ int    g_off[N_NODES];
__device__ int    g_cur[N_NODES];
__device__ int    g_part[256];
__device__ int    g_srcs[N_EDGES];

// Packed panel offsets (MUST match k_prep_all's layout!)
#define WT1_OFF 0          // Wl1|Wr1: 256x128
#define WT2_OFF 32768      // Wl2|Wr2: 256x128
#define WT3_OFF 65536      // Wl3|Wr3: 128x128
#define WT4_OFF 81920      // We1 top|bottom: 256x64
#define PREP_TOT 98304
#define PREP_THREADS (N_NODES > PREP_TOT ? N_NODES : PREP_TOT)

// ---------------- fused prep: zero ALL counts + build all 4 fp16 weight panels ---
__global__ void k_prep_all(const float* __restrict__ Wl1, const float* __restrict__ Wr1,
                           const float* __restrict__ Wl2, const float* __restrict__ Wr2,
                           const float* __restrict__ Wl3, const float* __restrict__ Wr3,
                           const float* __restrict__ We1) {
    int i = blockIdx.x * 256 + threadIdx.x;
    if (i < N_NODES) g_count[i] = 0;          // MUST cover all nodes (replay reset!)
    if (i >= PREP_TOT) return;
    float v;
    if (i < WT3_OFF) {
        const float* s1 = (i < WT2_OFF) ? Wl1 : Wl2;
        const float* s2 = (i < WT2_OFF) ? Wr1 : Wr2;
        int j = i & 32767;
        int mm = j >> 7;                       // 0..255
        int kk = j & 127;
        v = (mm < 128) ? s1[(size_t)kk * 128 + mm] : s2[(size_t)kk * 128 + (mm - 128)];
    } else if (i < WT4_OFF) {
        int j = i - WT3_OFF;                   // K=128, Mh=64
        int mm = j >> 7, kk = j & 127;
        v = (mm < 64) ? Wl3[(size_t)kk * 64 + mm] : Wr3[(size_t)kk * 64 + (mm - 64)];
    } else {
        int j = i - WT4_OFF;                   // K=64, Mh=128
        int mm = j >> 6, kk = j & 63;
        const float* s1 = We1;
        const float* s2 = We1 + 64 * 128;
        v = (mm < 128) ? s1[(size_t)kk * 128 + mm] : s2[(size_t)kk * 128 + (mm - 128)];
    }
    g_wth[i] = __float2half_rn(v);
}

// ---------------- CSR build ----------------
__global__ void k_count(const int* __restrict__ dst) {
    int i = blockIdx.x * blockDim.x + threadIdx.x;
    if (i < N_EDGES) atomicAdd(&g_count[dst[i]], 1);
}
__global__ void k_scan1() {
    __shared__ int sm[1024];
    int i = blockIdx.x * 1024 + threadIdx.x;
    int v = (i < N_NODES) ? g_count[i] : 0;
    sm[threadIdx.x] = v;
    __syncthreads();
    #pragma unroll
    for (int s = 1; s < 1024; s <<= 1) {
        int t = (threadIdx.x >= s) ? sm[threadIdx.x - s] : 0;
        __syncthreads();
        sm[threadIdx.x] += t;
        __syncthreads();
    }
    if (i < N_NODES) g_off[i] = sm[threadIdx.x] - v;
    if (threadIdx.x == 1023) g_part[blockIdx.x] = sm[1023];
}
// scan3 with inlined partial-prefix (replaces scan2+scan3)
__global__ void k_scan3() {
    __shared__ int red[32];
    int t = threadIdx.x, b = blockIdx.x;
    int v = (t < b) ? g_part[t] : 0;   // b <= 97 < 1024
    #pragma unroll
    for (int o = 16; o; o >>= 1) v += __shfl_xor_sync(0xFFFFFFFFu, v, o);
    if ((t & 31) == 0) red[t >> 5] = v;
    __syncthreads();
    if (t == 0) {
        int s = 0;
        #pragma unroll
        for (int w = 0; w < 32; w++) s += red[w];
        red[0] = s;
    }
    __syncthreads();
    int base = red[0];
    int i = b * 1024 + t;
    if (i < N_NODES) {
        int o = g_off[i] + base;
        g_off[i] = o;
        g_cur[i] = o;
    }
}
__global__ void k_fill(const int* __restrict__ src, const int* __restrict__ dst) {
    int i = blockIdx.x * blockDim.x + threadIdx.x;
    if (i < N_EDGES) {
        int d = dst[i];
        int p = atomicAdd(&g_cur[d], 1);
        g_srcs[p] = src[i];
    }
}

// ---------------- fp16 mma.sync m16n8k16 GEMM, all-fp16 epilogue ----------------
// C[Nrows, NOUT] = A[Nrows, K] @ Wt[NOUT, K]^T, fp32 accumulate.
// cols < SPLIT -> o1 (stride S1); cols >= SPLIT -> o2 (stride S2). Both fp16.
template<int K, typename AT>
__global__ __launch_bounds__(256, 2) void k_mma(const AT* __restrict__ A,
                                                const __half* __restrict__ Wt,
                                                __half* __restrict__ o1, int S1, int SPLIT,
                                                __half* __restrict__ o2, int S2,
                                                int Nrows) {
    constexpr int SA = K + 8;            // halves per row (stride)
    extern __shared__ __half sh[];
    __half* As = sh;                     // [128][SA]
    __half* Bs = sh + 128 * SA;          // [128][SA]

    const int tid  = threadIdx.x;
    const int lane = tid & 31, wid = tid >> 5;
    const int gid  = lane >> 2, tg = lane & 3;
    const int mrow = (wid & 3) * 32;
    const int ncol = (wid >> 2) * 64;
    const int row0 = blockIdx.x * 128;
    const int col0 = blockIdx.y * 128;

    if (sizeof(AT) == 4) {
        // fp32 input: convert during staging. 128*(K/4) float4, K/8 per thread.
        #pragma unroll
        for (int l = 0; l < K / 8; l++) {
            int f = tid + l * 256;
            int r = f / (K / 4), c4 = f % (K / 4);
            int grow = row0 + r;
            float4 v = make_float4(0.f, 0.f, 0.f, 0.f);
            if (grow < Nrows) v = *(const float4*)((const float*)A + (size_t)grow * K + c4 * 4);
            __half2 h0 = __floats2half2_rn(v.x, v.y);
            __half2 h1 = __floats2half2_rn(v.z, v.w);
            uint2 u;
            u.x = *(uint32_t*)&h0;
            u.y = *(uint32_t*)&h1;
            *(uint2*)(As + r * SA + c4 * 4) = u;
        }
    } else {
        // fp16 input: pure copy. 128*(K/8) uint4, K/16 per thread.
        #pragma unroll
        for (int l = 0; l < K / 16; l++) {
            int f = tid + l * 256;
            int r = f / (K / 8), c8 = f % (K / 8);
            int grow = row0 + r;
            uint4 v = make_uint4(0u, 0u, 0u, 0u);
            if (grow < Nrows) v = *(const uint4*)((const __half*)A + (size_t)grow * K + c8 * 8);
            *(uint4*)(As + r * SA + c8 * 8) = v;
        }
    }
    // stage B: pure copy
    #pragma unroll
    for (int l = 0; l < K / 16; l++) {
        int f = tid + l * 256;
        int r = f / (K / 8), c8 = f % (K / 8);
        uint4 v = *(const uint4*)(Wt + (size_t)(col0 + r) * K + c8 * 8);
        *(uint4*)(Bs + r * SA + c8 * 8) = v;
    }
    __syncthreads();

    float c[2][8][4];
    #pragma unroll
    for (int mt = 0; mt < 2; mt++)
        #pragma unroll
        for (int nt = 0; nt < 8; nt++)
            #pragma unroll
            for (int j = 0; j < 4; j++) c[mt][nt][j] = 0.f;

    #pragma unroll
    for (int ks = 0; ks < K / 16; ks++) {
        const int k0 = ks * 16;
        uint32_t a[2][4];
        #pragma unroll
        for (int mt = 0; mt < 2; mt++) {
            int r = mrow + mt * 16 + gid;
            a[mt][0] = *(const uint32_t*)(As + r * SA + k0 + 2 * tg);
            a[mt][1] = *(const uint32_t*)(As + (r + 8) * SA + k0 + 2 * tg);
            a[mt][2] = *(const uint32_t*)(As + r * SA + k0 + 8 + 2 * tg);
            a[mt][3] = *(const uint32_t*)(As + (r + 8) * SA + k0 + 8 + 2 * tg);
        }
        uint32_t b[8][2];
        #pragma unroll
        for (int nt = 0; nt < 8; nt++) {
            int rn = ncol + nt * 8 + gid;
            b[nt][0] = *(const uint32_t*)(Bs + rn * SA + k0 + 2 * tg);
            b[nt][1] = *(const uint32_t*)(Bs + rn * SA + k0 + 8 + 2 * tg);
        }
        #pragma unroll
        for (int mt = 0; mt < 2; mt++)
            #pragma unroll
            for (int nt = 0; nt < 8; nt++)
                asm volatile(
                    "mma.sync.aligned.m16n8k16.row.col.f32.f16.f16.f32 "
                    "{%0,%1,%2,%3}, {%4,%5,%6,%7}, {%8,%9}, {%0,%1,%2,%3};"
                    : "+f"(c[mt][nt][0]), "+f"(c[mt][nt][1]),
                      "+f"(c[mt][nt][2]), "+f"(c[mt][nt][3])
                    : "r"(a[mt][0]), "r"(a[mt][1]), "r"(a[mt][2]), "r"(a[mt][3]),
                      "r"(b[nt][0]), "r"(b[nt][1]));
    }

    // epilogue: (c0,c1)@r0, (c2,c3)@r1 at columns colg, colg+1 (all fp16 stores)
    #pragma unroll
    for (int mt = 0; mt < 2; mt++) {
        int r0 = row0 + mrow + mt * 16 + gid;
        int r1 = r0 + 8;
        #pragma unroll
        for (int nt = 0; nt < 8; nt++) {
            int colg = col0 + ncol + nt * 8 + 2 * tg;
            __half2 v0 = __halves2half2(__float2half_rn(c[mt][nt][0]), __float2half_rn(c[mt][nt][1]));
            __half2 v1 = __halves2half2(__float2half_rn(c[mt][nt][2]), __float2half_rn(c[mt][nt][3]));
            if (colg < SPLIT) {
                if (r0 < Nrows) *(__half2*)(o1 + (size_t)r0 * S1 + colg) = v0;
                if (r1 < Nrows) *(__half2*)(o1 + (size_t)r1 * S1 + colg) = v1;
            } else {
                int cf = colg - SPLIT;
                if (r0 < Nrows) *(__half2*)(o2 + (size_t)r0 * S2 + cf) = v0;
                if (r1 < Nrows) *(__half2*)(o2 + (size_t)r1 * S2 + cf) = v1;
            }
        }
    }
}

// ---------------- fused aggregation + combine (warp per node, fp16 gather) ------
// RES: 0 = none (writes outF float), 1 = fp32 residual, 2 = fp16 residual (write outH)
template<int C, int RES>
__global__ __launch_bounds__(256) void k_aggh(const float* __restrict__ bl,
                                              const float* __restrict__ gam,
                                              const float* __restrict__ bet,
                                              const float* __restrict__ hinF,
                                              const __half* __restrict__ hinH,
                                              __half* __restrict__ outH,
                                              float* __restrict__ outF,
                                              const __half* __restrict__ yh,
                                              const __half* __restrict__ yrh) {
    constexpr int V = C / 32;   // channels per lane: 4 (C=128) or 2 (C=64)
    int warp = (blockIdx.x * 256 + threadIdx.x) >> 5;
    int lane = threadIdx.x & 31;
    if (warp >= N_NODES) return;
    int n = warp;
    int beg = g_off[n], cnt = g_count[n];

    float acc[V];
    #pragma unroll
    for (int j = 0; j < V; j++) acc[j] = 0.f;

    for (int e0 = 0; e0 < cnt; e0 += 32) {
        int m = min(32, cnt - e0);
        int myidx = (lane < m) ? __ldg(&g_srcs[beg + e0 + lane]) : 0;
        int i = 0;
        for (; i + 4 <= m; i += 4) {
            int s0 = __shfl_sync(0xFFFFFFFFu, myidx, i);
            int s1 = __shfl_sync(0xFFFFFFFFu, myidx, i + 1);
            int s2 = __shfl_sync(0xFFFFFFFFu, myidx, i + 2);
            int s3 = __shfl_sync(0xFFFFFFFFu, myidx, i + 3);
            if (V == 4) {
                uint2 u0 = *(const uint2*)(yh + (size_t)s0 * C + lane * 4);
                uint2 u1 = *(const uint2*)(yh + (size_t)s1 * C + lane * 4);
                uint2 u2 = *(const uint2*)(yh + (size_t)s2 * C + lane * 4);
                uint2 u3 = *(const uint2*)(yh + (size_t)s3 * C + lane * 4);
                float2 a0 = __half22float2(*(__half2*)&u0.x), b0 = __half22float2(*(__half2*)&u0.y);
                float2 a1 = __half22float2(*(__half2*)&u1.x), b1 = __half22float2(*(__half2*)&u1.y);
                float2 a2 = __half22float2(*(__half2*)&u2.x), b2 = __half22float2(*(__half2*)&u2.y);
                float2 a3 = __half22float2(*(__half2*)&u3.x), b3 = __half22float2(*(__half2*)&u3.y);
                acc[0] += a0.x + a1.x + a2.x + a3.x;
                acc[1] += a0.y + a1.y + a2.y + a3.y;
                acc[2] += b0.x + b1.x + b2.x + b3.x;
                acc[3] += b0.y + b1.y + b2.y + b3.y;
            } else {
                uint32_t u0 = *(const uint32_t*)(yh + (size_t)s0 * C + lane * 2);
                uint32_t u1 = *(const uint32_t*)(yh + (size_t)s1 * C + lane * 2);
                uint32_t u2 = *(const uint32_t*)(yh + (size_t)s2 * C + lane * 2);
                uint32_t u3 = *(const uint32_t*)(yh + (size_t)s3 * C + lane * 2);
                float2 a0 = __half22float2(*(__half2*)&u0);
                float2 a1 = __half22float2(*(__half2*)&u1);
                float2 a2 = __half22float2(*(__half2*)&u2);
                float2 a3 = __half22float2(*(__half2*)&u3);
                acc[0] += a0.x + a1.x + a2.x + a3.x;
                acc[1] += a0.y + a1.y + a2.y + a3.y;
            }
        }
        for (; i < m; i++) {
            int s = __shfl_sync(0xFFFFFFFFu, myidx, i);
            if (V == 4) {
                uint2 u = *(const uint2*)(yh + (size_t)s * C + lane * 4);
                float2 a = __half22float2(*(__half2*)&u.x), b = __half22float2(*(__half2*)&u.y);
                acc[0] += a.x; acc[1] += a.y; acc[2] += b.x; acc[3] += b.y;
            } else {
                uint32_t u = *(const uint32_t*)(yh + (size_t)s * C + lane * 2);
                float2 a = __half22float2(*(__half2*)&u);
                acc[0] += a.x; acc[1] += a.y;
            }
        }
    }
    float inv = 1.0f / fmaxf((float)cnt, 1.0f);

    float o[V];
    {
        // root features (fp16, sequential)
        if (V == 4) {
            uint2 u = *(const uint2*)(yrh + (size_t)n * C + lane * 4);
            float2 a = __half22float2(*(__half2*)&u.x), b = __half22float2(*(__half2*)&u.y);
            o[0] = acc[0] * inv + bl[lane * 4 + 0] + a.x;
            o[1] = acc[1] * inv + bl[lane * 4 + 1] + a.y;
            o[2] = acc[2] * inv + bl[lane * 4 + 2] + b.x;
            o[3] = acc[3] * inv + bl[lane * 4 + 3] + b.y;
        } else {
            uint32_t u = *(const uint32_t*)(yrh + (size_t)n * C + lane * 2);
            float2 a = __half22float2(*(__half2*)&u);
            o[0] = acc[0] * inv + bl[lane * 2 + 0] + a.x;
            o[1] = acc[1] * inv + bl[lane * 2 + 1] + a.y;
        }
    }
    if (RES != 0) {
        const float s = rsqrtf(1.0f + BN_EPS);
        float h[V];
        if (RES == 1) {
            const float* hp = hinF + (size_t)n * C + lane * V;
            #pragma unroll
            for (int j = 0; j < V; j++) h[j] = hp[j];
        } else {
            uint2 u = *(const uint2*)(hinH + (size_t)n * C + lane * 4);
            float2 a = __half22float2(*(__half2*)&u.x), b = __half22float2(*(__half2*)&u.y);
            h[0] = a.x; h[1] = a.y; h[2] = b.x; h[3] = b.y;
        }
        #pragma unroll
        for (int j = 0; j < V; j++) {
            int ch = lane * V + j;
            o[j] = fmaxf(o[j] * (gam[ch] * s) + bet[ch], 0.f) + h[j];
        }
        // fp16 output
        if (V == 4) {
            __half2 h0 = __floats2half2_rn(o[0], o[1]);
            __half2 h1 = __floats2half2_rn(o[2], o[3]);
            uint2 u;
            u.x = *(uint32_t*)&h0;
            u.y = *(uint32_t*)&h1;
            *(uint2*)(outH + (size_t)n * C + lane * 4) = u;
        } else {
            __half2 h0 = __floats2half2_rn(o[0], o[1]);
            *(uint32_t*)(outH + (size_t)n * C + lane * 2) = *(uint32_t*)&h0;
        }
    } else {
        // fp32 output (z)
        if (V == 4) *(float4*)(outF + (size_t)n * C + lane * 4) = make_float4(o[0], o[1], o[2], o[3]);
        else        *(float2*)(outF + (size_t)n * C + lane * 2) = make_float2(o[0], o[1]);
    }
}

// ---------------- merged edge decode (pos + neg in one launch) ------------------
__global__ void k_decode2(const int* __restrict__ pos, const int* __restrict__ neg,
                          const float* __restrict__ be1,
                          const float* __restrict__ We2, const float* __restrict__ be2,
                          float* __restrict__ outpos, float* __restrict__ outneg,
                          const __half* __restrict__ yh) {
    int warp = (blockIdx.x * blockDim.x + threadIdx.x) >> 5;
    int lane = threadIdx.x & 31;
    if (warp >= N_POS + N_NEG) return;
    int s, d;
    float* op;
    if (warp < N_POS) {
        s = pos[warp]; d = pos[N_POS + warp]; op = outpos + warp;
    } else {
        int w = warp - N_POS;
        s = neg[w]; d = neg[N_NEG + w]; op = outneg + w;
    }
    uint2 up = *(const uint2*)(yh + (size_t)s * 256 + lane * 4);
    uint2 uq = *(const uint2*)(yh + (size_t)d * 256 + 128 + lane * 4);
    float2 p0 = __half22float2(*(__half2*)&up.x), p1 = __half22float2(*(__half2*)&up.y);
    float2 q0 = __half22float2(*(__half2*)&uq.x), q1 = __half22float2(*(__half2*)&uq.y);
    float4 bb = *(const float4*)(be1 + lane * 4);
    float4 w  = *(const float4*)(We2 + lane * 4);
    float sum = fmaxf(p0.x + q0.x + bb.x, 0.f) * w.x
              + fmaxf(p0.y + q0.y + bb.y, 0.f) * w.y
              + fmaxf(p1.x + q1.x + bb.z, 0.f) * w.z
              + fmaxf(p1.y + q1.y + bb.w, 0.f) * w.w;
    #pragma unroll
    for (int o = 16; o; o >>= 1) sum += __shfl_xor_sync(0xFFFFFFFFu, sum, o);
    if (lane == 0) *op = 1.0f / (1.0f + expf(-(sum + be2[0])));
}

// ---------------- host launcher ----------------
extern "C" void kernel_launch(void* const* d_in, const int* in_sizes, int n_in,
                              void* d_out, int out_size) {
    const float* x   = (const float*)d_in[0];
    const int*   ei  = (const int*)d_in[1];
    const int*   pos = (const int*)d_in[2];
    const int*   neg = (const int*)d_in[3];
    const float* Wl1 = (const float*)d_in[4];
    const float* bl1 = (const float*)d_in[5];
    const float* Wr1 = (const float*)d_in[6];
    const float* g1  = (const float*)d_in[7];
    const float* b1  = (const float*)d_in[8];
    const float* Wl2 = (const float*)d_in[9];
    const float* bl2 = (const float*)d_in[10];
    const float* Wr2 = (const float*)d_in[11];
    const float* g2  = (const float*)d_in[12];
    const float* b2  = (const float*)d_in[13];
    const float* Wl3 = (const float*)d_in[14];
    const float* bl3 = (const float*)d_in[15];
    const float* Wr3 = (const float*)d_in[16];
    const float* We1 = (const float*)d_in[17];
    const float* be1 = (const float*)d_in[18];
    const float* We2 = (const float*)d_in[19];
    const float* be2 = (const float*)d_in[20];

    float* out    = (float*)d_out;
    float* z      = out;
    float* outpos = out + (size_t)N_NODES * OUT_C;
    float* outneg = outpos + N_POS;

    __half *yh, *yrh, *hA, *hB, *wt;
    cudaGetSymbolAddress((void**)&yh, g_yh);
    cudaGetSymbolAddress((void**)&yrh, g_yrh);
    cudaGetSymbolAddress((void**)&hA, g_hA);
    cudaGetSymbolAddress((void**)&hB, g_hB);
    cudaGetSymbolAddress((void**)&wt, g_wth);
    __half* wt1 = wt + WT1_OFF;   // packed offsets — must match k_prep_all
    __half* wt2 = wt + WT2_OFF;
    __half* wt3 = wt + WT3_OFF;
    __half* wt4 = wt + WT4_OFF;

    const int SM128 = 2 * 128 * (128 + 8) * 2;  // 69632
    const int SM64  = 2 * 128 * (64 + 8) * 2;   // 36864
    cudaFuncSetAttribute(k_mma<128, float>,  cudaFuncAttributeMaxDynamicSharedMemorySize, SM128);
    cudaFuncSetAttribute(k_mma<128, __half>, cudaFuncAttributeMaxDynamicSharedMemorySize, SM128);
    cudaFuncSetAttribute(k_mma<64, float>,   cudaFuncAttributeMaxDynamicSharedMemorySize, SM64);

    const int EB = (N_EDGES + 255) / 256;
    const int SCAN_NB = (N_NODES + 1023) / 1024;
    const int GT = (N_NODES + 127) / 128;
    const int AGGB = (N_NODES * 32 + 255) / 256;

    // ---- prep (weights + zero ALL counts) + CSR build ----
    k_prep_all<<<(PREP_THREADS + 255) / 256, 256>>>(Wl1, Wr1, Wl2, Wr2, Wl3, Wr3, We1);
    k_count<<<EB, 256>>>(ei + N_EDGES);
    k_scan1<<<SCAN_NB, 1024>>>();
    k_scan3<<<SCAN_NB, 1024>>>();
    k_fill<<<EB, 256>>>(ei, ei + N_EDGES);

    dim3 gA(GT, 2);   // NOUT=256
    dim3 gB(GT, 1);   // NOUT=128

    // ---- layer 1: yl(cols<128)->yh, yr(cols>=128)->yrh ----
    k_mma<128, float><<<gA, 256, SM128>>>(x, wt1, yh, 128, 128, yrh, 128, N_NODES);
    k_aggh<128, 1><<<AGGB, 256>>>(bl1, g1, b1, x, nullptr, hA, nullptr, yh, yrh);

    // ---- layer 2 (fp16 input) ----
    k_mma<128, __half><<<gA, 256, SM128>>>(hA, wt2, yh, 128, 128, yrh, 128, N_NODES);
    k_aggh<128, 2><<<AGGB, 256>>>(bl2, g2, b2, nullptr, hA, hB, nullptr, yh, yrh);

    // ---- layer 3 (C=64, fp16 input, fp32 z output) ----
    k_mma<128, __half><<<gB, 256, SM128>>>(hB, wt3, yh, 64, 64, yrh, 64, N_NODES);
    k_aggh<64, 0><<<AGGB, 256>>>(bl3, nullptr, nullptr, nullptr, nullptr, nullptr, z, yh, yrh);

    // ---- decode prep: yh[n][0:128]=P, yh[n][128:256]=Q ----
    k_mma<64, float><<<gA, 256, SM64>>>(z, wt4, yh, 256, 256, nullptr, 0, N_NODES);

    // ---- decode (merged pos+neg) ----
    k_decode2<<<((N_POS + N_NEG) * 32 + 127) / 128, 128>>>(pos, neg, be1, We2, be2, outpos, outneg, yh);
}